// round 6
// baseline (speedup 1.0000x reference)
#include <cuda_runtime.h>
#include <cuda_bf16.h>
#include <math.h>
#include <stdint.h>
#include <stddef.h>

// Problem dims
#define Bsz 256
#define Ssz 512
#define Fdim 128
#define Hdim 128
#define G3  384   // 3*H

// Output layout (tuple flattened): h_enc, output, z, gamma, dis, dis_perm
#define OFF_HENC  ((size_t)0)
#define OFF_OUT   ((size_t)32768)                       // 256*128
#define OFF_Z     ((size_t)(32768 + 16777216))          // + 256*512*128
#define OFF_GAMMA ((size_t)(OFF_Z + 256*129))
#define OFF_DIS   ((size_t)(OFF_GAMMA + 256*4))
#define OFF_DISP  ((size_t)(OFF_DIS + 256*8*128))

typedef unsigned long long ull;

// Scratch (device globals; no allocations allowed)
__device__ float g_Genc[(size_t)Ssz * Bsz * G3];    // [t][b][g]  192 MB
__device__ float g_Hdec[(size_t)Ssz * Bsz * Hdim];  // [i][b][j]   64 MB
__device__ float g_Henc[Bsz * Hdim];
__device__ float g_Mf[G3 * Hdim];
__device__ float g_bf[G3];
__device__ int   g_perm[8 * Bsz];                   // [k][pos] -> batch idx

__device__ __forceinline__ float sigf(float x) { return 1.0f / (1.0f + expf(-x)); }

// ---- packed f32x2 helpers (FFMA2 only reachable via PTX fma.rn.f32x2) ----
__device__ __forceinline__ ull pk2(float lo, float hi) {
    ull r; asm("mov.b64 %0, {%1, %2};" : "=l"(r) : "f"(lo), "f"(hi)); return r;
}
__device__ __forceinline__ ull f2fma(ull a, ull b, ull c) {
    ull d; asm("fma.rn.f32x2 %0, %1, %2, %3;" : "=l"(d) : "l"(a), "l"(b), "l"(c)); return d;
}
__device__ __forceinline__ float psum(ull v) {
    float a, b; asm("mov.b64 {%0, %1}, %2;" : "=f"(a), "=f"(b) : "l"(v)); return a + b;
}

// ---------------------------------------------------------------------------
// Threefry2x32 core (20 rounds, exact JAX constants)
// ---------------------------------------------------------------------------
__device__ __forceinline__ uint2 threefry(unsigned k0, unsigned k1,
                                          unsigned x0, unsigned x1) {
    unsigned ks2 = k0 ^ k1 ^ 0x1BD11BDAu;
    x0 += k0; x1 += k1;
#define TFR(r) { x0 += x1; x1 = (x1 << (r)) | (x1 >> (32 - (r))); x1 ^= x0; }
    TFR(13) TFR(15) TFR(26) TFR(6)   x0 += k1;  x1 += ks2 + 1u;
    TFR(17) TFR(29) TFR(16) TFR(24)  x0 += ks2; x1 += k0 + 2u;
    TFR(13) TFR(15) TFR(26) TFR(6)   x0 += k0;  x1 += k1 + 3u;
    TFR(17) TFR(29) TFR(16) TFR(24)  x0 += k1;  x1 += ks2 + 4u;
    TFR(13) TFR(15) TFR(26) TFR(6)   x0 += ks2; x1 += k0 + 5u;
#undef TFR
    return make_uint2(x0, x1);
}

// JAX threefry_partitionable=True reproduction (verified passing in R5)
__global__ void perm_kernel(int* __restrict__ perm) {
    __shared__ unsigned sk[8][2];
    __shared__ unsigned bits[256];
    int t = threadIdx.x;
    if (t < 8) {
        uint2 pk = threefry(0u, 42u, 0u, (unsigned)t);   // perm_keys[t]
        uint2 s  = threefry(pk.x, pk.y, 0u, 1u);         // subkey = split(.)[1]
        sk[t][0] = s.x; sk[t][1] = s.y;
    }
    __syncthreads();
    for (int k = 0; k < 8; k++) {
        uint2 y = threefry(sk[k][0], sk[k][1], 0u, (unsigned)t);
        bits[t] = y.x ^ y.y;
        __syncthreads();
        unsigned mine = bits[t];
        int rank = 0;
        for (int j = 0; j < 256; j++) {
            unsigned o = bits[j];
            rank += (o < mine) || (o == mine && j < t);
        }
        perm[k * 256 + rank] = t;
        __syncthreads();
    }
}

// ---------------------------------------------------------------------------
// GEMM A (FFMA2): g_Genc[t*256+b][g] = x[b,t,:] . enc_Wih[g,:] + enc_bih[g]
// smem layout [row][kpair] (pad 17 ull) so k-pairs feed fma.rn.f32x2 directly.
// ---------------------------------------------------------------------------
__global__ void __launch_bounds__(256) gemm_gi(const float* __restrict__ X,
                                               const float* __restrict__ W,
                                               const float* __restrict__ bias) {
    __shared__ __align__(16) ull As2[64 * 17];
    __shared__ __align__(16) ull Bs2[64 * 17];
    int tid = threadIdx.x;
    int tx = tid & 15, ty = tid >> 4;
    int rBase = blockIdx.x * 64;
    int n0 = blockIdx.y * 64;
    ull accP[4][4];
#pragma unroll
    for (int i = 0; i < 4; i++)
#pragma unroll
        for (int j = 0; j < 4; j++) accP[i][j] = 0ULL;  // (0.f, 0.f)

    for (int kc = 0; kc < 4; kc++) {
        int k0 = kc * 32;
#pragma unroll
        for (int p = 0; p < 2; p++) {
            int l = tid + p * 256;
            int row = l >> 3, qq = l & 7;
            int r = rBase + row;
            const float* xp = X + (((size_t)(r & 255) * 512 + (r >> 8)) << 7);
            float4 v = *(const float4*)&xp[k0 + qq * 4];
            As2[row * 17 + qq * 2]     = pk2(v.x, v.y);
            As2[row * 17 + qq * 2 + 1] = pk2(v.z, v.w);
        }
#pragma unroll
        for (int p = 0; p < 2; p++) {
            int l = tid + p * 256;
            int n = l >> 3, qq = l & 7;
            float4 v = *(const float4*)&W[(size_t)(n0 + n) * 128 + k0 + qq * 4];
            Bs2[n * 17 + qq * 2]     = pk2(v.x, v.y);
            Bs2[n * 17 + qq * 2 + 1] = pk2(v.z, v.w);
        }
        __syncthreads();
#pragma unroll
        for (int kp = 0; kp < 16; kp++) {
            ull a0 = As2[(ty * 4 + 0) * 17 + kp];
            ull a1 = As2[(ty * 4 + 1) * 17 + kp];
            ull a2 = As2[(ty * 4 + 2) * 17 + kp];
            ull a3 = As2[(ty * 4 + 3) * 17 + kp];
            ull b0 = Bs2[(tx * 4 + 0) * 17 + kp];
            ull b1 = Bs2[(tx * 4 + 1) * 17 + kp];
            ull b2 = Bs2[(tx * 4 + 2) * 17 + kp];
            ull b3 = Bs2[(tx * 4 + 3) * 17 + kp];
            accP[0][0] = f2fma(a0, b0, accP[0][0]); accP[0][1] = f2fma(a0, b1, accP[0][1]);
            accP[0][2] = f2fma(a0, b2, accP[0][2]); accP[0][3] = f2fma(a0, b3, accP[0][3]);
            accP[1][0] = f2fma(a1, b0, accP[1][0]); accP[1][1] = f2fma(a1, b1, accP[1][1]);
            accP[1][2] = f2fma(a1, b2, accP[1][2]); accP[1][3] = f2fma(a1, b3, accP[1][3]);
            accP[2][0] = f2fma(a2, b0, accP[2][0]); accP[2][1] = f2fma(a2, b1, accP[2][1]);
            accP[2][2] = f2fma(a2, b2, accP[2][2]); accP[2][3] = f2fma(a2, b3, accP[2][3]);
            accP[3][0] = f2fma(a3, b0, accP[3][0]); accP[3][1] = f2fma(a3, b1, accP[3][1]);
            accP[3][2] = f2fma(a3, b2, accP[3][2]); accP[3][3] = f2fma(a3, b3, accP[3][3]);
        }
        __syncthreads();
    }
    float b0 = bias[n0 + tx * 4 + 0], b1 = bias[n0 + tx * 4 + 1];
    float b2 = bias[n0 + tx * 4 + 2], b3 = bias[n0 + tx * 4 + 3];
#pragma unroll
    for (int i = 0; i < 4; i++) {
        int r = rBase + ty * 4 + i;
        float4 v = make_float4(psum(accP[i][0]) + b0, psum(accP[i][1]) + b1,
                               psum(accP[i][2]) + b2, psum(accP[i][3]) + b3);
        *(float4*)&g_Genc[(size_t)r * 384 + n0 + tx * 4] = v;
    }
}

// ---------------------------------------------------------------------------
// out-GEMM (FFMA2): o_i = Hdec[i] @ out_W^T + out_b ; writes output[b][511-i][:]
// ---------------------------------------------------------------------------
__global__ void __launch_bounds__(256) gemm_out(const float* __restrict__ W,
                                                const float* __restrict__ bias,
                                                float* __restrict__ out) {
    __shared__ __align__(16) ull As2[64 * 17];
    __shared__ __align__(16) ull Bs2[64 * 17];
    int tid = threadIdx.x;
    int tx = tid & 15, ty = tid >> 4;
    int rBase = blockIdx.x * 64;
    int n0 = blockIdx.y * 64;
    ull accP[4][4];
#pragma unroll
    for (int i = 0; i < 4; i++)
#pragma unroll
        for (int j = 0; j < 4; j++) accP[i][j] = 0ULL;

    for (int kc = 0; kc < 4; kc++) {
        int k0 = kc * 32;
#pragma unroll
        for (int p = 0; p < 2; p++) {
            int l = tid + p * 256;
            int row = l >> 3, qq = l & 7;
            int r = rBase + row;
            float4 v = *(const float4*)&g_Hdec[(size_t)r * 128 + k0 + qq * 4];
            As2[row * 17 + qq * 2]     = pk2(v.x, v.y);
            As2[row * 17 + qq * 2 + 1] = pk2(v.z, v.w);
        }
#pragma unroll
        for (int p = 0; p < 2; p++) {
            int l = tid + p * 256;
            int n = l >> 3, qq = l & 7;
            float4 v = *(const float4*)&W[(size_t)(n0 + n) * 128 + k0 + qq * 4];
            Bs2[n * 17 + qq * 2]     = pk2(v.x, v.y);
            Bs2[n * 17 + qq * 2 + 1] = pk2(v.z, v.w);
        }
        __syncthreads();
#pragma unroll
        for (int kp = 0; kp < 16; kp++) {
            ull a0 = As2[(ty * 4 + 0) * 17 + kp];
            ull a1 = As2[(ty * 4 + 1) * 17 + kp];
            ull a2 = As2[(ty * 4 + 2) * 17 + kp];
            ull a3 = As2[(ty * 4 + 3) * 17 + kp];
            ull b0 = Bs2[(tx * 4 + 0) * 17 + kp];
            ull b1 = Bs2[(tx * 4 + 1) * 17 + kp];
            ull b2 = Bs2[(tx * 4 + 2) * 17 + kp];
            ull b3 = Bs2[(tx * 4 + 3) * 17 + kp];
            accP[0][0] = f2fma(a0, b0, accP[0][0]); accP[0][1] = f2fma(a0, b1, accP[0][1]);
            accP[0][2] = f2fma(a0, b2, accP[0][2]); accP[0][3] = f2fma(a0, b3, accP[0][3]);
            accP[1][0] = f2fma(a1, b0, accP[1][0]); accP[1][1] = f2fma(a1, b1, accP[1][1]);
            accP[1][2] = f2fma(a1, b2, accP[1][2]); accP[1][3] = f2fma(a1, b3, accP[1][3]);
            accP[2][0] = f2fma(a2, b0, accP[2][0]); accP[2][1] = f2fma(a2, b1, accP[2][1]);
            accP[2][2] = f2fma(a2, b2, accP[2][2]); accP[2][3] = f2fma(a2, b3, accP[2][3]);
            accP[3][0] = f2fma(a3, b0, accP[3][0]); accP[3][1] = f2fma(a3, b1, accP[3][1]);
            accP[3][2] = f2fma(a3, b2, accP[3][2]); accP[3][3] = f2fma(a3, b3, accP[3][3]);
        }
        __syncthreads();
    }
    float b0 = bias[n0 + tx * 4 + 0], b1 = bias[n0 + tx * 4 + 1];
    float b2 = bias[n0 + tx * 4 + 2], b3 = bias[n0 + tx * 4 + 3];
#pragma unroll
    for (int i = 0; i < 4; i++) {
        int r = rBase + ty * 4 + i;
        int is = r >> 8, bb = r & 255;
        size_t orow = (size_t)(bb * 512 + (511 - is)) * 128;
        float4 v = make_float4(psum(accP[i][0]) + b0, psum(accP[i][1]) + b1,
                               psum(accP[i][2]) + b2, psum(accP[i][3]) + b3);
        *(float4*)&out[OFF_OUT + orow + n0 + tx * 4] = v;
    }
}

// ---------------------------------------------------------------------------
// Fold: Mf[g][j] = sum_f dec_Wih[g,f]*out_W[f,j];  bf[g] = dec_bih[g] + dec_Wih[g,:].out_b
// ---------------------------------------------------------------------------
__global__ void fold_kernel(const float* __restrict__ dWih, const float* __restrict__ outW,
                            const float* __restrict__ outb, const float* __restrict__ dbih) {
    int g = blockIdx.x, j = threadIdx.x;
    __shared__ float wrow[128];
    __shared__ float red[128];
    wrow[j] = dWih[g * 128 + j];
    __syncthreads();
    float acc = 0.0f;
#pragma unroll 8
    for (int f = 0; f < 128; f++) acc = fmaf(wrow[f], outW[f * 128 + j], acc);
    g_Mf[g * 128 + j] = acc;
    red[j] = wrow[j] * outb[j];
    __syncthreads();
    for (int s = 64; s > 0; s >>= 1) {
        if (j < s) red[j] += red[j + s];
        __syncthreads();
    }
    if (j == 0) g_bf[g] = dbih[g] + red[0];
}

// ---------------------------------------------------------------------------
// Encoder recurrence (FFMA2 over k-pairs): 128 CTAs x 384 threads; 2 batch/CTA.
// Thread g holds Whh row g as 64 packed pairs in registers.
// ---------------------------------------------------------------------------
__global__ void __launch_bounds__(384, 1) enc_kernel(const float* __restrict__ Whh,
                                                     const float* __restrict__ bhh) {
    __shared__ __align__(16) float h_sm[2][128];
    __shared__ float gh_sm[2][384];
    int g = threadIdx.x;
    int b0 = blockIdx.x * 2;
    ull w2[64];
    {
        const ull* wrow = (const ull*)Whh + (size_t)g * 64;
#pragma unroll
        for (int kp = 0; kp < 64; kp++) w2[kp] = wrow[kp];
    }
    float bg = bhh[g];
    int bb = g >> 7, j = g & 127;
    if (g < 256) h_sm[bb][j] = 0.0f;
    __syncthreads();

    for (int t = 0; t < 512; t++) {
        float gi_r = 0.f, gi_z = 0.f, gi_n = 0.f;
        if (g < 256) {
            const float* gp = g_Genc + ((size_t)t * 256 + b0 + bb) * 384;
            gi_r = gp[j]; gi_z = gp[128 + j]; gi_n = gp[256 + j];
        }
        ull a0 = pk2(bg, 0.f), a1 = pk2(bg, 0.f);
#pragma unroll
        for (int q = 0; q < 32; q++) {
            ulonglong2 h0 = *(const ulonglong2*)&h_sm[0][4 * q];
            ulonglong2 h1 = *(const ulonglong2*)&h_sm[1][4 * q];
            a0 = f2fma(w2[2 * q],     h0.x, a0);
            a1 = f2fma(w2[2 * q],     h1.x, a1);
            a0 = f2fma(w2[2 * q + 1], h0.y, a0);
            a1 = f2fma(w2[2 * q + 1], h1.y, a1);
        }
        gh_sm[0][g] = psum(a0);
        gh_sm[1][g] = psum(a1);
        __syncthreads();
        if (g < 256) {
            float r = sigf(gi_r + gh_sm[bb][j]);
            float z = sigf(gi_z + gh_sm[bb][128 + j]);
            float n = tanhf(gi_n + r * gh_sm[bb][256 + j]);
            h_sm[bb][j] = (1.0f - z) * n + z * h_sm[bb][j];
        }
        __syncthreads();
    }
    if (g < 256) g_Henc[(b0 + bb) * 128 + j] = h_sm[bb][j];
}

// ---------------------------------------------------------------------------
// Decoder recurrence (FFMA2). Mfused packed in regs, dec_Whh in smem as
// ulonglong2 wq[32][384] (two k-pairs per 16B lane load, conflict-free).
// Stores h_i (pre-update) to g_Hdec[i][b][:].
// ---------------------------------------------------------------------------
__global__ void __launch_bounds__(384, 1) dec_kernel(const float* __restrict__ Whh,
                                                     const float* __restrict__ bhh) {
    extern __shared__ __align__(16) unsigned char dsm[];
    ulonglong2* wq = (ulonglong2*)dsm;                 // [32][384] -> 196608 B
    float* hsm = (float*)(dsm + 196608);               // [2][128]  -> 1024 B
    float* gis = hsm + 256;                            // [2][384]
    float* ghs = gis + 768;                            // [2][384]
    int g = threadIdx.x;
    int b0 = blockIdx.x * 2;
    int bb = g >> 7, j = g & 127;

    ull w2[64];
    {
        const ull* wrow = (const ull*)g_Mf + (size_t)g * 64;
#pragma unroll
        for (int kp = 0; kp < 64; kp++) w2[kp] = wrow[kp];
    }
    float bfg = g_bf[g];
    float bhg = bhh[g];

    // wq[q][g] = (pair 2q, pair 2q+1) of Whh row g  (coalesced global reads)
    for (int idx = g; idx < 384 * 32; idx += 384) {
        int gg = idx >> 5, q = idx & 31;
        wq[q * 384 + gg] = ((const ulonglong2*)Whh)[(size_t)gg * 32 + q];
    }
    if (g < 256) hsm[g] = g_Henc[b0 * 128 + g];
    __syncthreads();

    for (int i = 0; i < 512; i++) {
        if (g < 256) g_Hdec[((size_t)i * 256 + b0 + bb) * 128 + j] = hsm[g];
        ull gi0 = pk2(bfg, 0.f), gi1 = pk2(bfg, 0.f);
        ull gh0 = pk2(bhg, 0.f), gh1 = pk2(bhg, 0.f);
#pragma unroll
        for (int q = 0; q < 32; q++) {
            ulonglong2 wv = wq[q * 384 + g];
            ulonglong2 h0 = *(const ulonglong2*)&hsm[4 * q];
            ulonglong2 h1 = *(const ulonglong2*)&hsm[128 + 4 * q];
            gi0 = f2fma(w2[2 * q],     h0.x, gi0);
            gi1 = f2fma(w2[2 * q],     h1.x, gi1);
            gh0 = f2fma(wv.x,          h0.x, gh0);
            gh1 = f2fma(wv.x,          h1.x, gh1);
            gi0 = f2fma(w2[2 * q + 1], h0.y, gi0);
            gi1 = f2fma(w2[2 * q + 1], h1.y, gi1);
            gh0 = f2fma(wv.y,          h0.y, gh0);
            gh1 = f2fma(wv.y,          h1.y, gh1);
        }
        gis[g] = psum(gi0); gis[384 + g] = psum(gi1);
        ghs[g] = psum(gh0); ghs[384 + g] = psum(gh1);
        __syncthreads();
        if (g < 256) {
            int base = bb * 384;
            float r = sigf(gis[base + j] + ghs[base + j]);
            float z = sigf(gis[base + 128 + j] + ghs[base + 128 + j]);
            float n = tanhf(gis[base + 256 + j] + r * ghs[base + 256 + j]);
            hsm[g] = (1.0f - z) * n + z * hsm[g];
        }
        __syncthreads();
    }
}

// ---------------------------------------------------------------------------
// Epilogue A: cosine, h_enc copy, LN/attn/dis/z/gamma. One block per batch elem.
// ---------------------------------------------------------------------------
__device__ __forceinline__ float bsum(float v, float* red) {
    int t = threadIdx.x;
    __syncthreads();
    red[t] = v;
    __syncthreads();
    for (int s = 128; s > 0; s >>= 1) {
        if (t < s) red[t] += red[t + s];
        __syncthreads();
    }
    return red[0];
}

__global__ void __launch_bounds__(256) epiA(
    const float* __restrict__ X,
    const float* __restrict__ protos,
    const float* __restrict__ lnzw, const float* __restrict__ lnzb,
    const float* __restrict__ lnpw, const float* __restrict__ lnpb,
    const float* __restrict__ lnaw, const float* __restrict__ lnab,
    const float* __restrict__ beta,
    const float* __restrict__ e1W, const float* __restrict__ e1b,
    const float* __restrict__ e2W, const float* __restrict__ e2b,
    float* __restrict__ out) {
    int b = blockIdx.x, t = threadIdx.x;
    __shared__ float red[256];
    __shared__ float zln[128];
    __shared__ float pl[8][128];
    __shared__ float dotk[8];
    __shared__ float attnv[8];
    __shared__ float zfull[129];
    __shared__ float h1s[10];
    __shared__ float lg[4];

    // rec_cosine
    const float* a = X + (size_t)b * 65536;
    const float* o = out + OFF_OUT + (size_t)b * 65536;
    float sab = 0.f, saa = 0.f, sbb = 0.f;
    for (int i = t; i < 65536; i += 256) {
        float av = a[i], bv = o[i];
        sab = fmaf(av, bv, sab);
        saa = fmaf(av, av, saa);
        sbb = fmaf(bv, bv, sbb);
    }
    sab = bsum(sab, red);
    saa = bsum(saa, red);
    sbb = bsum(sbb, red);
    float rc = sab / (fmaxf(sqrtf(saa), 1e-8f) * fmaxf(sqrtf(sbb), 1e-8f));

    // h_enc copy + LN(z)
    float h = (t < 128) ? g_Henc[b * 128 + t] : 0.0f;
    if (t < 128) out[OFF_HENC + b * 128 + t] = h;
    float mu = bsum(h, red) * (1.0f / 128.0f);
    float d = (t < 128) ? (h - mu) : 0.0f;
    float var = bsum(d * d, red) * (1.0f / 128.0f);
    if (t < 128) zln[t] = lnzw[t] * d * rsqrtf(var + 1e-12f) + lnzb[t];

    // LN(prototypes)
    for (int k = 0; k < 8; k++) {
        float p = (t < 128) ? protos[k * 128 + t] : 0.0f;
        float pu = bsum(p, red) * (1.0f / 128.0f);
        float pd = (t < 128) ? (p - pu) : 0.0f;
        float pv = bsum(pd * pd, red) * (1.0f / 128.0f);
        if (t < 128) pl[k][t] = lnpw[t] * pd * rsqrtf(pv + 1e-12f) + lnpb[t];
    }
    __syncthreads();

    // attn = softmax(z_ln @ prot_ln^T / sqrt(H))
    for (int k = 0; k < 8; k++) {
        float pp = (t < 128) ? zln[t] * pl[k][t] : 0.0f;
        float s = bsum(pp, red);
        if (t == 0) dotk[k] = s * 0.08838834764831845f;  // 1/sqrt(128)
    }
    __syncthreads();
    if (t < 8) {
        float m = -1e30f;
        for (int kk = 0; kk < 8; kk++) m = fmaxf(m, dotk[kk]);
        float s = 0.f;
        for (int kk = 0; kk < 8; kk++) s += expf(dotk[kk] - m);
        attnv[t] = expf(dotk[t] - m) / s;
    }
    __syncthreads();

    // dis + z mean
    float zacc = 0.0f;
    for (int k = 0; k < 8; k++) {
        float v = (t < 128) ? (beta[k * 128 + t] + attnv[k] * h) : 0.0f;
        float vu = bsum(v, red) * (1.0f / 128.0f);
        float vd = (t < 128) ? (v - vu) : 0.0f;
        float vv = bsum(vd * vd, red) * (1.0f / 128.0f);
        if (t < 128) {
            float dval = lnaw[t] * vd * rsqrtf(vv + 1e-12f) + lnab[t];
            out[OFF_DIS + ((size_t)b * 8 + k) * 128 + t] = dval;
            zacc += dval;
        }
    }
    if (t < 128) {
        float zv = zacc * 0.125f;
        zfull[t] = zv;
        out[OFF_Z + (size_t)b * 129 + t] = zv;
    }
    if (t == 0) {
        zfull[128] = rc;
        out[OFF_Z + (size_t)b * 129 + 128] = rc;
    }
    __syncthreads();

    if (t < 10) {
        float acc = e1b[t];
        for (int i = 0; i < 129; i++) acc = fmaf(e1W[t * 129 + i], zfull[i], acc);
        h1s[t] = tanhf(acc);
    }
    __syncthreads();
    if (t < 4) {
        float acc = e2b[t];
        for (int i = 0; i < 10; i++) acc = fmaf(e2W[t * 10 + i], h1s[i], acc);
        lg[t] = acc;
    }
    __syncthreads();
    if (t < 4) {
        float m = fmaxf(fmaxf(lg[0], lg[1]), fmaxf(lg[2], lg[3]));
        float s = expf(lg[0] - m) + expf(lg[1] - m) + expf(lg[2] - m) + expf(lg[3] - m);
        out[OFF_GAMMA + (size_t)b * 4 + t] = expf(lg[t] - m) / s;
    }
}

// dis_perm[b,k,:] = dis[perm_k[b], k, :]
__global__ void epiB(float* __restrict__ out, const int* __restrict__ perm) {
    int b = blockIdx.x;
    for (int e = threadIdx.x; e < 1024; e += blockDim.x) {
        int k = e >> 7, j = e & 127;
        int src = perm[k * 256 + b];
        out[OFF_DISP + ((size_t)b * 8 + k) * 128 + j] =
            out[OFF_DIS + ((size_t)src * 8 + k) * 128 + j];
    }
}

// ---------------------------------------------------------------------------
extern "C" void kernel_launch(void* const* d_in, const int* in_sizes, int n_in,
                              void* d_out, int out_size) {
    const float* input   = (const float*)d_in[0];
    const float* enc_Wih = (const float*)d_in[1];
    const float* enc_Whh = (const float*)d_in[2];
    const float* enc_bih = (const float*)d_in[3];
    const float* enc_bhh = (const float*)d_in[4];
    const float* dec_Wih = (const float*)d_in[5];
    const float* dec_Whh = (const float*)d_in[6];
    const float* dec_bih = (const float*)d_in[7];
    const float* dec_bhh = (const float*)d_in[8];
    const float* out_W   = (const float*)d_in[9];
    const float* out_b   = (const float*)d_in[10];
    const float* protos  = (const float*)d_in[11];
    const float* lnz_w   = (const float*)d_in[12];
    const float* lnz_b   = (const float*)d_in[13];
    const float* lnp_w   = (const float*)d_in[14];
    const float* lnp_b   = (const float*)d_in[15];
    const float* lna_w   = (const float*)d_in[16];
    const float* lna_b   = (const float*)d_in[17];
    const float* beta    = (const float*)d_in[18];
    const float* est1_W  = (const float*)d_in[19];
    const float* est1_b  = (const float*)d_in[20];
    const float* est2_W  = (const float*)d_in[21];
    const float* est2_b  = (const float*)d_in[22];
    float* out = (float*)d_out;

    int* perm_ptr = nullptr;
    cudaGetSymbolAddress((void**)&perm_ptr, g_perm);

    cudaFuncSetAttribute(dec_kernel, cudaFuncAttributeMaxDynamicSharedMemorySize, 204288);

    // 1. Encoder input gates (time-parallel GEMM, FFMA2)
    gemm_gi<<<dim3(2048, 6), 256>>>(input, enc_Wih, enc_bih);
    // 2. Encoder recurrence (FFMA2)
    enc_kernel<<<128, 384>>>(enc_Whh, enc_bhh);
    // 3. Fold output projection into decoder input weights
    fold_kernel<<<384, 128>>>(dec_Wih, out_W, out_b, dec_bih);
    // 4. Decoder recurrence (FFMA2, stores h_i trajectory)
    dec_kernel<<<128, 384, 204288>>>(dec_Whh, dec_bhh);
    // 5. Output projection for all 512 steps (parallel GEMM, FFMA2)
    gemm_out<<<dim3(2048, 2), 256>>>(out_W, out_b, out);
    // 6. JAX-exact permutations (threefry_partitionable scheme)
    perm_kernel<<<1, 256>>>(perm_ptr);
    // 7. Epilogue: cosine, LN, attention, dis, z, gamma
    epiA<<<256, 256>>>(input, protos, lnz_w, lnz_b, lnp_w, lnp_b, lna_w, lna_b,
                       beta, est1_W, est1_b, est2_W, est2_b, out);
    // 8. dis_perm gather
    epiB<<<256, 256>>>(out, perm_ptr);
}

// round 7
// speedup vs baseline: 1.0359x; 1.0359x over previous
#include <cuda_runtime.h>
#include <cuda_bf16.h>
#include <math.h>
#include <stdint.h>
#include <stddef.h>

// Problem dims
#define Bsz 256
#define Ssz 512
#define Fdim 128
#define Hdim 128
#define G3  384   // 3*H

// Output layout (tuple flattened): h_enc, output, z, gamma, dis, dis_perm
#define OFF_HENC  ((size_t)0)
#define OFF_OUT   ((size_t)32768)                       // 256*128
#define OFF_Z     ((size_t)(32768 + 16777216))          // + 256*512*128
#define OFF_GAMMA ((size_t)(OFF_Z + 256*129))
#define OFF_DIS   ((size_t)(OFF_GAMMA + 256*4))
#define OFF_DISP  ((size_t)(OFF_DIS + 256*8*128))

typedef unsigned long long ull;

// Scratch (device globals; no allocations allowed)
__device__ float g_Genc[(size_t)Ssz * Bsz * G3];    // [t][b][g]  192 MB
__device__ float g_Hdec[(size_t)Ssz * Bsz * Hdim];  // [i][b][j]   64 MB
__device__ float g_Henc[Bsz * Hdim];
__device__ float g_Mf[G3 * Hdim];
__device__ float g_bf[G3];
__device__ int   g_perm[8 * Bsz];                   // [k][pos] -> batch idx

__device__ __forceinline__ float sigf(float x) { return 1.0f / (1.0f + expf(-x)); }

// ---- packed f32x2 helpers (FFMA2 only reachable via PTX fma.rn.f32x2) ----
__device__ __forceinline__ ull pk2(float lo, float hi) {
    ull r; asm("mov.b64 %0, {%1, %2};" : "=l"(r) : "f"(lo), "f"(hi)); return r;
}
__device__ __forceinline__ ull f2fma(ull a, ull b, ull c) {
    ull d; asm("fma.rn.f32x2 %0, %1, %2, %3;" : "=l"(d) : "l"(a), "l"(b), "l"(c)); return d;
}
__device__ __forceinline__ float psum(ull v) {
    float a, b; asm("mov.b64 {%0, %1}, %2;" : "=f"(a), "=f"(b) : "l"(v)); return a + b;
}

// ---------------------------------------------------------------------------
// Threefry2x32 core (20 rounds, exact JAX constants)
// ---------------------------------------------------------------------------
__device__ __forceinline__ uint2 threefry(unsigned k0, unsigned k1,
                                          unsigned x0, unsigned x1) {
    unsigned ks2 = k0 ^ k1 ^ 0x1BD11BDAu;
    x0 += k0; x1 += k1;
#define TFR(r) { x0 += x1; x1 = (x1 << (r)) | (x1 >> (32 - (r))); x1 ^= x0; }
    TFR(13) TFR(15) TFR(26) TFR(6)   x0 += k1;  x1 += ks2 + 1u;
    TFR(17) TFR(29) TFR(16) TFR(24)  x0 += ks2; x1 += k0 + 2u;
    TFR(13) TFR(15) TFR(26) TFR(6)   x0 += k0;  x1 += k1 + 3u;
    TFR(17) TFR(29) TFR(16) TFR(24)  x0 += k1;  x1 += ks2 + 4u;
    TFR(13) TFR(15) TFR(26) TFR(6)   x0 += ks2; x1 += k0 + 5u;
#undef TFR
    return make_uint2(x0, x1);
}

// JAX threefry_partitionable=True reproduction (verified passing in R5)
__global__ void perm_kernel(int* __restrict__ perm) {
    __shared__ unsigned sk[8][2];
    __shared__ unsigned bits[256];
    int t = threadIdx.x;
    if (t < 8) {
        uint2 pk = threefry(0u, 42u, 0u, (unsigned)t);   // perm_keys[t]
        uint2 s  = threefry(pk.x, pk.y, 0u, 1u);         // subkey = split(.)[1]
        sk[t][0] = s.x; sk[t][1] = s.y;
    }
    __syncthreads();
    for (int k = 0; k < 8; k++) {
        uint2 y = threefry(sk[k][0], sk[k][1], 0u, (unsigned)t);
        bits[t] = y.x ^ y.y;
        __syncthreads();
        unsigned mine = bits[t];
        int rank = 0;
        for (int j = 0; j < 256; j++) {
            unsigned o = bits[j];
            rank += (o < mine) || (o == mine && j < t);
        }
        perm[k * 256 + rank] = t;
        __syncthreads();
    }
}

// ---------------------------------------------------------------------------
// GEMM A (FFMA2, [kpair][row] layout): g_Genc[r][g] = x . enc_Wih[g,:] + b
// Layout keeps 4 microtile rows contiguous -> 2x LDS.128 per operand per kp
// (same load count as scalar version) with half the FMA instructions.
// PAD=66 (even) keeps 16B alignment of ull2 loads; stores are <=4-way once.
// ---------------------------------------------------------------------------
#define GPAD 66
__global__ void __launch_bounds__(256) gemm_gi(const float* __restrict__ X,
                                               const float* __restrict__ W,
                                               const float* __restrict__ bias) {
    __shared__ __align__(16) ull As2[16 * GPAD + 4];
    __shared__ __align__(16) ull Bs2[16 * GPAD + 4];
    int tid = threadIdx.x;
    int tx = tid & 15, ty = tid >> 4;
    int rBase = blockIdx.x * 64;
    int n0 = blockIdx.y * 64;
    ull accP[4][4];
#pragma unroll
    for (int i = 0; i < 4; i++)
#pragma unroll
        for (int j = 0; j < 4; j++) accP[i][j] = 0ULL;

    for (int kc = 0; kc < 4; kc++) {
        int k0 = kc * 32;
#pragma unroll
        for (int p = 0; p < 2; p++) {
            int l = tid + p * 256;
            int row = l >> 3, qq = l & 7;     // qq: float4 index along k
            int r = rBase + row;
            const float* xp = X + (((size_t)(r & 255) * 512 + (r >> 8)) << 7);
            float4 v = *(const float4*)&xp[k0 + qq * 4];
            As2[(2 * qq) * GPAD + row]     = pk2(v.x, v.y);
            As2[(2 * qq + 1) * GPAD + row] = pk2(v.z, v.w);
        }
#pragma unroll
        for (int p = 0; p < 2; p++) {
            int l = tid + p * 256;
            int n = l >> 3, qq = l & 7;
            float4 v = *(const float4*)&W[(size_t)(n0 + n) * 128 + k0 + qq * 4];
            Bs2[(2 * qq) * GPAD + n]     = pk2(v.x, v.y);
            Bs2[(2 * qq + 1) * GPAD + n] = pk2(v.z, v.w);
        }
        __syncthreads();
#pragma unroll
        for (int kp = 0; kp < 16; kp++) {
            ulonglong2 aLo = *(const ulonglong2*)&As2[kp * GPAD + ty * 4];
            ulonglong2 aHi = *(const ulonglong2*)&As2[kp * GPAD + ty * 4 + 2];
            ulonglong2 bLo = *(const ulonglong2*)&Bs2[kp * GPAD + tx * 4];
            ulonglong2 bHi = *(const ulonglong2*)&Bs2[kp * GPAD + tx * 4 + 2];
            accP[0][0] = f2fma(aLo.x, bLo.x, accP[0][0]); accP[0][1] = f2fma(aLo.x, bLo.y, accP[0][1]);
            accP[0][2] = f2fma(aLo.x, bHi.x, accP[0][2]); accP[0][3] = f2fma(aLo.x, bHi.y, accP[0][3]);
            accP[1][0] = f2fma(aLo.y, bLo.x, accP[1][0]); accP[1][1] = f2fma(aLo.y, bLo.y, accP[1][1]);
            accP[1][2] = f2fma(aLo.y, bHi.x, accP[1][2]); accP[1][3] = f2fma(aLo.y, bHi.y, accP[1][3]);
            accP[2][0] = f2fma(aHi.x, bLo.x, accP[2][0]); accP[2][1] = f2fma(aHi.x, bLo.y, accP[2][1]);
            accP[2][2] = f2fma(aHi.x, bHi.x, accP[2][2]); accP[2][3] = f2fma(aHi.x, bHi.y, accP[2][3]);
            accP[3][0] = f2fma(aHi.y, bLo.x, accP[3][0]); accP[3][1] = f2fma(aHi.y, bLo.y, accP[3][1]);
            accP[3][2] = f2fma(aHi.y, bHi.x, accP[3][2]); accP[3][3] = f2fma(aHi.y, bHi.y, accP[3][3]);
        }
        __syncthreads();
    }
    float b0 = bias[n0 + tx * 4 + 0], b1 = bias[n0 + tx * 4 + 1];
    float b2 = bias[n0 + tx * 4 + 2], b3 = bias[n0 + tx * 4 + 3];
#pragma unroll
    for (int i = 0; i < 4; i++) {
        int r = rBase + ty * 4 + i;
        float4 v = make_float4(psum(accP[i][0]) + b0, psum(accP[i][1]) + b1,
                               psum(accP[i][2]) + b2, psum(accP[i][3]) + b3);
        *(float4*)&g_Genc[(size_t)r * 384 + n0 + tx * 4] = v;
    }
}

// ---------------------------------------------------------------------------
// out-GEMM (FFMA2, same layout): o_i = Hdec[i] @ out_W^T + out_b
// ---------------------------------------------------------------------------
__global__ void __launch_bounds__(256) gemm_out(const float* __restrict__ W,
                                                const float* __restrict__ bias,
                                                float* __restrict__ out) {
    __shared__ __align__(16) ull As2[16 * GPAD + 4];
    __shared__ __align__(16) ull Bs2[16 * GPAD + 4];
    int tid = threadIdx.x;
    int tx = tid & 15, ty = tid >> 4;
    int rBase = blockIdx.x * 64;
    int n0 = blockIdx.y * 64;
    ull accP[4][4];
#pragma unroll
    for (int i = 0; i < 4; i++)
#pragma unroll
        for (int j = 0; j < 4; j++) accP[i][j] = 0ULL;

    for (int kc = 0; kc < 4; kc++) {
        int k0 = kc * 32;
#pragma unroll
        for (int p = 0; p < 2; p++) {
            int l = tid + p * 256;
            int row = l >> 3, qq = l & 7;
            int r = rBase + row;
            float4 v = *(const float4*)&g_Hdec[(size_t)r * 128 + k0 + qq * 4];
            As2[(2 * qq) * GPAD + row]     = pk2(v.x, v.y);
            As2[(2 * qq + 1) * GPAD + row] = pk2(v.z, v.w);
        }
#pragma unroll
        for (int p = 0; p < 2; p++) {
            int l = tid + p * 256;
            int n = l >> 3, qq = l & 7;
            float4 v = *(const float4*)&W[(size_t)(n0 + n) * 128 + k0 + qq * 4];
            Bs2[(2 * qq) * GPAD + n]     = pk2(v.x, v.y);
            Bs2[(2 * qq + 1) * GPAD + n] = pk2(v.z, v.w);
        }
        __syncthreads();
#pragma unroll
        for (int kp = 0; kp < 16; kp++) {
            ulonglong2 aLo = *(const ulonglong2*)&As2[kp * GPAD + ty * 4];
            ulonglong2 aHi = *(const ulonglong2*)&As2[kp * GPAD + ty * 4 + 2];
            ulonglong2 bLo = *(const ulonglong2*)&Bs2[kp * GPAD + tx * 4];
            ulonglong2 bHi = *(const ulonglong2*)&Bs2[kp * GPAD + tx * 4 + 2];
            accP[0][0] = f2fma(aLo.x, bLo.x, accP[0][0]); accP[0][1] = f2fma(aLo.x, bLo.y, accP[0][1]);
            accP[0][2] = f2fma(aLo.x, bHi.x, accP[0][2]); accP[0][3] = f2fma(aLo.x, bHi.y, accP[0][3]);
            accP[1][0] = f2fma(aLo.y, bLo.x, accP[1][0]); accP[1][1] = f2fma(aLo.y, bLo.y, accP[1][1]);
            accP[1][2] = f2fma(aLo.y, bHi.x, accP[1][2]); accP[1][3] = f2fma(aLo.y, bHi.y, accP[1][3]);
            accP[2][0] = f2fma(aHi.x, bLo.x, accP[2][0]); accP[2][1] = f2fma(aHi.x, bLo.y, accP[2][1]);
            accP[2][2] = f2fma(aHi.x, bHi.x, accP[2][2]); accP[2][3] = f2fma(aHi.x, bHi.y, accP[2][3]);
            accP[3][0] = f2fma(aHi.y, bLo.x, accP[3][0]); accP[3][1] = f2fma(aHi.y, bLo.y, accP[3][1]);
            accP[3][2] = f2fma(aHi.y, bHi.x, accP[3][2]); accP[3][3] = f2fma(aHi.y, bHi.y, accP[3][3]);
        }
        __syncthreads();
    }
    float b0 = bias[n0 + tx * 4 + 0], b1 = bias[n0 + tx * 4 + 1];
    float b2 = bias[n0 + tx * 4 + 2], b3 = bias[n0 + tx * 4 + 3];
#pragma unroll
    for (int i = 0; i < 4; i++) {
        int r = rBase + ty * 4 + i;
        int is = r >> 8, bb = r & 255;
        size_t orow = (size_t)(bb * 512 + (511 - is)) * 128;
        float4 v = make_float4(psum(accP[i][0]) + b0, psum(accP[i][1]) + b1,
                               psum(accP[i][2]) + b2, psum(accP[i][3]) + b3);
        *(float4*)&out[OFF_OUT + orow + n0 + tx * 4] = v;
    }
}

// ---------------------------------------------------------------------------
// Fold: Mf[g][j] = sum_f dec_Wih[g,f]*out_W[f,j];  bf[g] = dec_bih[g] + dec_Wih[g,:].out_b
// ---------------------------------------------------------------------------
__global__ void fold_kernel(const float* __restrict__ dWih, const float* __restrict__ outW,
                            const float* __restrict__ outb, const float* __restrict__ dbih) {
    int g = blockIdx.x, j = threadIdx.x;
    __shared__ float wrow[128];
    __shared__ float red[128];
    wrow[j] = dWih[g * 128 + j];
    __syncthreads();
    float acc = 0.0f;
#pragma unroll 8
    for (int f = 0; f < 128; f++) acc = fmaf(wrow[f], outW[f * 128 + j], acc);
    g_Mf[g * 128 + j] = acc;
    red[j] = wrow[j] * outb[j];
    __syncthreads();
    for (int s = 64; s > 0; s >>= 1) {
        if (j < s) red[j] += red[j + s];
        __syncthreads();
    }
    if (j == 0) g_bf[g] = dbih[g] + red[0];
}

// ---------------------------------------------------------------------------
// Encoder recurrence (FFMA2 over k-pairs): 128 CTAs x 384 threads; 2 batch/CTA.
// Thread g holds Whh row g as 64 packed pairs in registers.
// ---------------------------------------------------------------------------
__global__ void __launch_bounds__(384, 1) enc_kernel(const float* __restrict__ Whh,
                                                     const float* __restrict__ bhh) {
    __shared__ __align__(16) float h_sm[2][128];
    __shared__ float gh_sm[2][384];
    int g = threadIdx.x;
    int b0 = blockIdx.x * 2;
    ull w2[64];
    {
        const ull* wrow = (const ull*)Whh + (size_t)g * 64;
#pragma unroll
        for (int kp = 0; kp < 64; kp++) w2[kp] = wrow[kp];
    }
    float bg = bhh[g];
    int bb = g >> 7, j = g & 127;
    if (g < 256) h_sm[bb][j] = 0.0f;
    __syncthreads();

    for (int t = 0; t < 512; t++) {
        float gi_r = 0.f, gi_z = 0.f, gi_n = 0.f;
        if (g < 256) {
            const float* gp = g_Genc + ((size_t)t * 256 + b0 + bb) * 384;
            gi_r = gp[j]; gi_z = gp[128 + j]; gi_n = gp[256 + j];
        }
        ull a0 = pk2(bg, 0.f), a1 = pk2(bg, 0.f);
#pragma unroll
        for (int q = 0; q < 32; q++) {
            ulonglong2 h0 = *(const ulonglong2*)&h_sm[0][4 * q];
            ulonglong2 h1 = *(const ulonglong2*)&h_sm[1][4 * q];
            a0 = f2fma(w2[2 * q],     h0.x, a0);
            a1 = f2fma(w2[2 * q],     h1.x, a1);
            a0 = f2fma(w2[2 * q + 1], h0.y, a0);
            a1 = f2fma(w2[2 * q + 1], h1.y, a1);
        }
        gh_sm[0][g] = psum(a0);
        gh_sm[1][g] = psum(a1);
        __syncthreads();
        if (g < 256) {
            float r = sigf(gi_r + gh_sm[bb][j]);
            float z = sigf(gi_z + gh_sm[bb][128 + j]);
            float n = tanhf(gi_n + r * gh_sm[bb][256 + j]);
            h_sm[bb][j] = (1.0f - z) * n + z * h_sm[bb][j];
        }
        __syncthreads();
    }
    if (g < 256) g_Henc[(b0 + bb) * 128 + j] = h_sm[bb][j];
}

// ---------------------------------------------------------------------------
// Decoder recurrence (FFMA2). Mfused packed in regs, dec_Whh in smem as
// ulonglong2 wq[32][384]. Inner loop grouped (2 k-quads per group):
// loads first, then load-INDEPENDENT gi FMAs (register weights), then the
// load-dependent gh FMAs — gives each warp ready work while its wq loads
// sit in the crossbar queue. h_new stored to g_Hdec straight from registers.
// ---------------------------------------------------------------------------
__global__ void __launch_bounds__(384, 1) dec_kernel(const float* __restrict__ Whh,
                                                     const float* __restrict__ bhh) {
    extern __shared__ __align__(16) unsigned char dsm[];
    ulonglong2* wq = (ulonglong2*)dsm;                 // [32][384] -> 196608 B
    float* hsm = (float*)(dsm + 196608);               // [2][128]
    float* gis = hsm + 256;                            // [2][384]
    float* ghs = gis + 768;                            // [2][384]
    int g = threadIdx.x;
    int b0 = blockIdx.x * 2;
    int bb = g >> 7, j = g & 127;

    ull w2[64];
    {
        const ull* wrow = (const ull*)g_Mf + (size_t)g * 64;
#pragma unroll
        for (int kp = 0; kp < 64; kp++) w2[kp] = wrow[kp];
    }
    float bfg = g_bf[g];
    float bhg = bhh[g];

    // wq[q][g] = (pair 2q, pair 2q+1) of Whh row g  (coalesced global reads)
    for (int idx = g; idx < 384 * 32; idx += 384) {
        int gg = idx >> 5, q = idx & 31;
        wq[q * 384 + gg] = ((const ulonglong2*)Whh)[(size_t)gg * 32 + q];
    }
    float h_init = 0.f;
    if (g < 256) {
        h_init = g_Henc[b0 * 128 + g];
        hsm[g] = h_init;
        g_Hdec[((size_t)0 * 256 + b0 + bb) * 128 + j] = h_init;  // state entering step 0
    }
    __syncthreads();

    for (int i = 0; i < 512; i++) {
        ull gi0 = pk2(bfg, 0.f), gi1 = pk2(bfg, 0.f);
        ull gh0 = pk2(bhg, 0.f), gh1 = pk2(bhg, 0.f);
#pragma unroll
        for (int grp = 0; grp < 16; grp++) {
            // loads for this group (wq distinct 16B/lane; h broadcast)
            ulonglong2 wvA = wq[(2 * grp) * 384 + g];
            ulonglong2 wvB = wq[(2 * grp + 1) * 384 + g];
            ulonglong2 h0A = *(const ulonglong2*)&hsm[8 * grp];
            ulonglong2 h0B = *(const ulonglong2*)&hsm[8 * grp + 4];
            ulonglong2 h1A = *(const ulonglong2*)&hsm[128 + 8 * grp];
            ulonglong2 h1B = *(const ulonglong2*)&hsm[128 + 8 * grp + 4];
            // gi FMAs: independent of wq loads (register weights)
            gi0 = f2fma(w2[4 * grp],     h0A.x, gi0);
            gi1 = f2fma(w2[4 * grp],     h1A.x, gi1);
            gi0 = f2fma(w2[4 * grp + 1], h0A.y, gi0);
            gi1 = f2fma(w2[4 * grp + 1], h1A.y, gi1);
            gi0 = f2fma(w2[4 * grp + 2], h0B.x, gi0);
            gi1 = f2fma(w2[4 * grp + 2], h1B.x, gi1);
            gi0 = f2fma(w2[4 * grp + 3], h0B.y, gi0);
            gi1 = f2fma(w2[4 * grp + 3], h1B.y, gi1);
            // gh FMAs: consume the wq loads
            gh0 = f2fma(wvA.x, h0A.x, gh0);
            gh1 = f2fma(wvA.x, h1A.x, gh1);
            gh0 = f2fma(wvA.y, h0A.y, gh0);
            gh1 = f2fma(wvA.y, h1A.y, gh1);
            gh0 = f2fma(wvB.x, h0B.x, gh0);
            gh1 = f2fma(wvB.x, h1B.x, gh1);
            gh0 = f2fma(wvB.y, h0B.y, gh0);
            gh1 = f2fma(wvB.y, h1B.y, gh1);
        }
        gis[g] = psum(gi0); gis[384 + g] = psum(gi1);
        ghs[g] = psum(gh0); ghs[384 + g] = psum(gh1);
        __syncthreads();
        if (g < 256) {
            int base = bb * 384;
            float r = sigf(gis[base + j] + ghs[base + j]);
            float z = sigf(gis[base + 128 + j] + ghs[base + 128 + j]);
            float n = tanhf(gis[base + 256 + j] + r * ghs[base + 256 + j]);
            float h_new = (1.0f - z) * n + z * hsm[g];
            hsm[g] = h_new;
            if (i < 511)
                g_Hdec[((size_t)(i + 1) * 256 + b0 + bb) * 128 + j] = h_new;
        }
        __syncthreads();
    }
}

// ---------------------------------------------------------------------------
// Epilogue A: cosine, h_enc copy, LN/attn/dis/z/gamma. One block per batch elem.
// ---------------------------------------------------------------------------
__device__ __forceinline__ float bsum(float v, float* red) {
    int t = threadIdx.x;
    __syncthreads();
    red[t] = v;
    __syncthreads();
    for (int s = 128; s > 0; s >>= 1) {
        if (t < s) red[t] += red[t + s];
        __syncthreads();
    }
    return red[0];
}

__global__ void __launch_bounds__(256) epiA(
    const float* __restrict__ X,
    const float* __restrict__ protos,
    const float* __restrict__ lnzw, const float* __restrict__ lnzb,
    const float* __restrict__ lnpw, const float* __restrict__ lnpb,
    const float* __restrict__ lnaw, const float* __restrict__ lnab,
    const float* __restrict__ beta,
    const float* __restrict__ e1W, const float* __restrict__ e1b,
    const float* __restrict__ e2W, const float* __restrict__ e2b,
    float* __restrict__ out) {
    int b = blockIdx.x, t = threadIdx.x;
    __shared__ float red[256];
    __shared__ float zln[128];
    __shared__ float pl[8][128];
    __shared__ float dotk[8];
    __shared__ float attnv[8];
    __shared__ float zfull[129];
    __shared__ float h1s[10];
    __shared__ float lg[4];

    // rec_cosine
    const float* a = X + (size_t)b * 65536;
    const float* o = out + OFF_OUT + (size_t)b * 65536;
    float sab = 0.f, saa = 0.f, sbb = 0.f;
    for (int i = t; i < 65536; i += 256) {
        float av = a[i], bv = o[i];
        sab = fmaf(av, bv, sab);
        saa = fmaf(av, av, saa);
        sbb = fmaf(bv, bv, sbb);
    }
    sab = bsum(sab, red);
    saa = bsum(saa, red);
    sbb = bsum(sbb, red);
    float rc = sab / (fmaxf(sqrtf(saa), 1e-8f) * fmaxf(sqrtf(sbb), 1e-8f));

    // h_enc copy + LN(z)
    float h = (t < 128) ? g_Henc[b * 128 + t] : 0.0f;
    if (t < 128) out[OFF_HENC + b * 128 + t] = h;
    float mu = bsum(h, red) * (1.0f / 128.0f);
    float d = (t < 128) ? (h - mu) : 0.0f;
    float var = bsum(d * d, red) * (1.0f / 128.0f);
    if (t < 128) zln[t] = lnzw[t] * d * rsqrtf(var + 1e-12f) + lnzb[t];

    // LN(prototypes)
    for (int k = 0; k < 8; k++) {
        float p = (t < 128) ? protos[k * 128 + t] : 0.0f;
        float pu = bsum(p, red) * (1.0f / 128.0f);
        float pd = (t < 128) ? (p - pu) : 0.0f;
        float pv = bsum(pd * pd, red) * (1.0f / 128.0f);
        if (t < 128) pl[k][t] = lnpw[t] * pd * rsqrtf(pv + 1e-12f) + lnpb[t];
    }
    __syncthreads();

    // attn = softmax(z_ln @ prot_ln^T / sqrt(H))
    for (int k = 0; k < 8; k++) {
        float pp = (t < 128) ? zln[t] * pl[k][t] : 0.0f;
        float s = bsum(pp, red);
        if (t == 0) dotk[k] = s * 0.08838834764831845f;  // 1/sqrt(128)
    }
    __syncthreads();
    if (t < 8) {
        float m = -1e30f;
        for (int kk = 0; kk < 8; kk++) m = fmaxf(m, dotk[kk]);
        float s = 0.f;
        for (int kk = 0; kk < 8; kk++) s += expf(dotk[kk] - m);
        attnv[t] = expf(dotk[t] - m) / s;
    }
    __syncthreads();

    // dis + z mean
    float zacc = 0.0f;
    for (int k = 0; k < 8; k++) {
        float v = (t < 128) ? (beta[k * 128 + t] + attnv[k] * h) : 0.0f;
        float vu = bsum(v, red) * (1.0f / 128.0f);
        float vd = (t < 128) ? (v - vu) : 0.0f;
        float vv = bsum(vd * vd, red) * (1.0f / 128.0f);
        if (t < 128) {
            float dval = lnaw[t] * vd * rsqrtf(vv + 1e-12f) + lnab[t];
            out[OFF_DIS + ((size_t)b * 8 + k) * 128 + t] = dval;
            zacc += dval;
        }
    }
    if (t < 128) {
        float zv = zacc * 0.125f;
        zfull[t] = zv;
        out[OFF_Z + (size_t)b * 129 + t] = zv;
    }
    if (t == 0) {
        zfull[128] = rc;
        out[OFF_Z + (size_t)b * 129 + 128] = rc;
    }
    __syncthreads();

    if (t < 10) {
        float acc = e1b[t];
        for (int i = 0; i < 129; i++) acc = fmaf(e1W[t * 129 + i], zfull[i], acc);
        h1s[t] = tanhf(acc);
    }
    __syncthreads();
    if (t < 4) {
        float acc = e2b[t];
        for (int i = 0; i < 10; i++) acc = fmaf(e2W[t * 10 + i], h1s[i], acc);
        lg[t] = acc;
    }
    __syncthreads();
    if (t < 4) {
        float m = fmaxf(fmaxf(lg[0], lg[1]), fmaxf(lg[2], lg[3]));
        float s = expf(lg[0] - m) + expf(lg[1] - m) + expf(lg[2] - m) + expf(lg[3] - m);
        out[OFF_GAMMA + (size_t)b * 4 + t] = expf(lg[t] - m) / s;
    }
}

// dis_perm[b,k,:] = dis[perm_k[b], k, :]
__global__ void epiB(float* __restrict__ out, const int* __restrict__ perm) {
    int b = blockIdx.x;
    for (int e = threadIdx.x; e < 1024; e += blockDim.x) {
        int k = e >> 7, j = e & 127;
        int src = perm[k * 256 + b];
        out[OFF_DISP + ((size_t)b * 8 + k) * 128 + j] =
            out[OFF_DIS + ((size_t)src * 8 + k) * 128 + j];
    }
}

// ---------------------------------------------------------------------------
extern "C" void kernel_launch(void* const* d_in, const int* in_sizes, int n_in,
                              void* d_out, int out_size) {
    const float* input   = (const float*)d_in[0];
    const float* enc_Wih = (const float*)d_in[1];
    const float* enc_Whh = (const float*)d_in[2];
    const float* enc_bih = (const float*)d_in[3];
    const float* enc_bhh = (const float*)d_in[4];
    const float* dec_Wih = (const float*)d_in[5];
    const float* dec_Whh = (const float*)d_in[6];
    const float* dec_bih = (const float*)d_in[7];
    const float* dec_bhh = (const float*)d_in[8];
    const float* out_W   = (const float*)d_in[9];
    const float* out_b   = (const float*)d_in[10];
    const float* protos  = (const float*)d_in[11];
    const float* lnz_w   = (const float*)d_in[12];
    const float* lnz_b   = (const float*)d_in[13];
    const float* lnp_w   = (const float*)d_in[14];
    const float* lnp_b   = (const float*)d_in[15];
    const float* lna_w   = (const float*)d_in[16];
    const float* lna_b   = (const float*)d_in[17];
    const float* beta    = (const float*)d_in[18];
    const float* est1_W  = (const float*)d_in[19];
    const float* est1_b  = (const float*)d_in[20];
    const float* est2_W  = (const float*)d_in[21];
    const float* est2_b  = (const float*)d_in[22];
    float* out = (float*)d_out;

    int* perm_ptr = nullptr;
    cudaGetSymbolAddress((void**)&perm_ptr, g_perm);

    cudaFuncSetAttribute(dec_kernel, cudaFuncAttributeMaxDynamicSharedMemorySize, 204288);

    // 1. Encoder input gates (time-parallel GEMM, FFMA2)
    gemm_gi<<<dim3(2048, 6), 256>>>(input, enc_Wih, enc_bih);
    // 2. Encoder recurrence (FFMA2)
    enc_kernel<<<128, 384>>>(enc_Whh, enc_bhh);
    // 3. Fold output projection into decoder input weights
    fold_kernel<<<384, 128>>>(dec_Wih, out_W, out_b, dec_bih);
    // 4. Decoder recurrence (FFMA2, grouped loads/gi/gh, stores h trajectory)
    dec_kernel<<<128, 384, 204288>>>(dec_Whh, dec_bhh);
    // 5. Output projection for all 512 steps (parallel GEMM, FFMA2)
    gemm_out<<<dim3(2048, 2), 256>>>(out_W, out_b, out);
    // 6. JAX-exact permutations (threefry_partitionable scheme)
    perm_kernel<<<1, 256>>>(perm_ptr);
    // 7. Epilogue: cosine, LN, attention, dis, z, gamma
    epiA<<<256, 256>>>(input, protos, lnz_w, lnz_b, lnp_w, lnp_b, lna_w, lna_b,
                       beta, est1_W, est1_b, est2_W, est2_b, out);
    // 8. dis_perm gather
    epiB<<<256, 256>>>(out, perm_ptr);
}